// round 3
// baseline (speedup 1.0000x reference)
#include <cuda_runtime.h>

// ----------------------------------------------------------------------------
// complex_feature_renet — GB300 sm_103a
// Strategy: keep activations in [H][C][B*L] layout; convs = per-output-h SGEMM
// (M=C_out, K=khv*C_in, N=B*L), linears = row-batched GEMM. fp32 with packed
// fma.rn.f32x2 (FFMA2) inner loops.
// ----------------------------------------------------------------------------

#define BFIX 1024

// intermediates in [H][C][B][L] layout
__device__ float g_t0 [5 * 5   * BFIX * 127]; // conv0a out
__device__ float g_t1 [5 * 5   * BFIX * 81 ]; // lin0 out
__device__ float g_t2 [5 * 25  * BFIX * 81 ]; // conv0b out -> x1 (after +y)
__device__ float g_t3 [5 * 1   * BFIX * 81 ]; // lin r0 out
__device__ float g_t5 [5 * 75  * BFIX * 81 ]; // conv1 out
__device__ float g_t6 [5 * 75  * BFIX * 41 ]; // lin1 out
__device__ float g_t7 [5 * 150 * BFIX * 41 ]; // conv2 out -> x2
__device__ float g_t8 [5 * 25  * BFIX * 41 ]; // lin ra out
__device__ float g_t9 [4 * 300 * BFIX * 41 ]; // conv3 out
__device__ float g_t10[4 * 300 * BFIX * 18 ]; // lin2 out
__device__ float g_t12[5 * 150 * BFIX * 18 ]; // lin rb out

// folded conv weights: wp[o][dh][i] from w[o][i][dh]
__device__ float g_wp0b[25  * 15 ];
__device__ float g_wp1 [75  * 75 ];
__device__ float g_wp2 [150 * 225];
__device__ float g_wp3 [300 * 300];
__device__ float g_wp4 [512 * 600];
__device__ float g_wpb [512 * 450];

// ---------------- f32x2 helpers ----------------
__device__ __forceinline__ unsigned long long pack2(float x, float y) {
    unsigned long long r;
    asm("mov.b64 %0, {%1, %2};" : "=l"(r) : "f"(x), "f"(y));
    return r;
}
__device__ __forceinline__ void fma2(unsigned long long& c, unsigned long long a,
                                     unsigned long long b) {
    asm("fma.rn.f32x2 %0, %1, %2, %0;" : "+l"(c) : "l"(a), "l"(b));
}
__device__ __forceinline__ float2 unpack2(unsigned long long v) {
    float2 r;
    asm("mov.b64 {%0, %1}, %2;" : "=f"(r.x), "=f"(r.y) : "l"(v));
    return r;
}

// ---------------- weight fold kernel ----------------
__global__ void permute_w_kernel(const float* __restrict__ w, float* __restrict__ wp,
                                 int O, int C, int KH) {
    int idx = blockIdx.x * blockDim.x + threadIdx.x;
    int tot = O * C * KH;
    if (idx >= tot) return;
    int o = idx / (KH * C);
    int rem = idx - o * (KH * C);
    int dh = rem / C;
    int i = rem - dh * C;
    wp[idx] = w[(o * C + i) * KH + dh];
}

// ---------------- conv0a: x[B,1,5,127] -> t0[5][5][B][127] ----------------
__global__ void conv0a_kernel(const float* __restrict__ x, const float* __restrict__ w,
                              const float* __restrict__ bias, float* __restrict__ out,
                              int B) {
    int n = blockIdx.x * blockDim.x + threadIdx.x;
    int N = B * 127;
    if (n >= N) return;
    int b = n / 127, l = n - b * 127;
    float xv[5];
#pragma unroll
    for (int h = 0; h < 5; h++) xv[h] = x[(b * 5 + h) * 127 + l];
    float wv[5][3];
#pragma unroll
    for (int c = 0; c < 5; c++)
#pragma unroll
        for (int dh = 0; dh < 3; dh++) wv[c][dh] = w[c * 3 + dh];
#pragma unroll
    for (int ho = 0; ho < 5; ho++) {
#pragma unroll
        for (int c = 0; c < 5; c++) {
            float acc = bias[c];
#pragma unroll
            for (int dh = 0; dh < 3; dh++) {
                int hi = ho + dh - 1;
                if (hi >= 0 && hi < 5) acc = fmaf(wv[c][dh], xv[hi], acc);
            }
            out[(size_t)(ho * 5 + c) * N + n] = acc;
        }
    }
}

// ---------------- lin kernel: out[r][o] = sum_k in[r][k]*W[o][k] + b[o] ------
// optional relu; optional row remap r=(b*H+h) -> (h*B+b) for the raw-x linear.
__global__ __launch_bounds__(256) void lin_kernel(
    const float* __restrict__ in, const float* __restrict__ W,
    const float* __restrict__ bias, float* __restrict__ out,
    int R, int K, int O, int Kp, int BR, int relu, int Hremap, int B) {
    __shared__ __align__(16) float sm[11776];
    float* Ws = sm;
    float* Rs = sm + O * Kp;
    int t = threadIdx.x;
    for (int idx = t; idx < O * Kp; idx += 256) {
        int o = idx / Kp, k = idx - o * Kp;
        Ws[idx] = (k < K) ? W[o * K + k] : 0.f;
    }
    int r0 = blockIdx.x * BR;
    int nr = R - r0;
    if (nr > BR) nr = BR;
    for (int idx = t; idx < nr * Kp; idx += 256) {
        int r = idx / Kp, k = idx - r * Kp;
        Rs[idx] = (k < K) ? in[(size_t)(r0 + r) * K + k] : 0.f;
    }
    __syncthreads();
    for (int idx = t; idx < nr * O; idx += 256) {
        int r = idx / O, o = idx - r * O;
        const float4* wr = reinterpret_cast<const float4*>(Ws + o * Kp);
        const float4* xr = reinterpret_cast<const float4*>(Rs + r * Kp);
        float sx = 0.f, sy = 0.f, sz = 0.f, sw = 0.f;
        int kq = Kp >> 2;
#pragma unroll 4
        for (int k = 0; k < kq; k++) {
            float4 w4 = wr[k], x4 = xr[k];
            sx = fmaf(w4.x, x4.x, sx);
            sy = fmaf(w4.y, x4.y, sy);
            sz = fmaf(w4.z, x4.z, sz);
            sw = fmaf(w4.w, x4.w, sw);
        }
        float acc = bias[o] + ((sx + sy) + (sz + sw));
        if (relu) acc = fmaxf(acc, 0.f);
        int orow = r0 + r;
        if (Hremap) {
            int bb = orow / Hremap;
            int h = orow - bb * Hremap;
            orow = h * B + bb;
        }
        out[(size_t)orow * O + o] = acc;
    }
}

// ---------------- conv GEMM ----------------
// in  : [H_in][C_in][N]   (N = B*L, divisible by 128)
// Wp  : [C_out][KH*C_in]  folded weights
// out : [H_out][C_out][N] (or final output layout if flags&2)
// flags: 1 = accumulate into existing out, 2 = final [B,512,3,18] store
template <int BM, int TM>
__global__ __launch_bounds__(256, 2) void conv_gemm_kernel(
    const float* __restrict__ A, const float* __restrict__ bias,
    const float* __restrict__ Bin, float* __restrict__ Cout,
    int C_in, int C_out, int KH, int pad, int H_in, int N, int flags) {
    constexpr int BN = 128, BK = 16, TN = 8;
    constexpr int ASR = BM + 4;          // padded A smem stride
    constexpr int TPR = 256 / BM;        // threads per A row
    constexpr int CH = BM / 16;          // A elems per thread per tile

    __shared__ __align__(16) float As[BK * ASR];
    __shared__ __align__(16) float Bs[BK * BN];

    const int t = threadIdx.x;
    const int ho = blockIdx.z;
    const int bm0 = blockIdx.y * BM;
    const int bn0 = blockIdx.x * BN;

    const int hs = ho - pad;
    int h0 = hs > 0 ? hs : 0;
    int hend = hs + KH;
    if (hend > H_in) hend = H_in;
    const int khv = hend - h0;
    const int K = khv * C_in;
    const int ldA = KH * C_in;
    const float* Ap = A + (h0 - hs) * C_in;
    const float* Bp = Bin + (size_t)(h0 * C_in) * N;

    const int am = t / TPR;
    const int ak0 = (t % TPR) * CH;
    const int bk = t / 32;          // 0..7 ; second element uses bk+8
    const int bn4 = (t % 32) * 4;

    const int tidm = t / 16, tidn = t % 16;
    const int tm0 = tidm * TM, tn0 = tidn * TN;

    unsigned long long acc[TM][4];
#pragma unroll
    for (int i = 0; i < TM; i++)
#pragma unroll
        for (int j = 0; j < 4; j++) acc[i][j] = 0ull;

    const int nk = (K + BK - 1) / BK;
    const int gm = bm0 + am;

    // tile 0 -> smem
#pragma unroll
    for (int j = 0; j < CH; j++) {
        int gk = ak0 + j;
        float v = 0.f;
        if (gm < C_out && gk < K) v = Ap[(size_t)gm * ldA + gk];
        As[gk * ASR + am] = v;
    }
#pragma unroll
    for (int i = 0; i < 2; i++) {
        int k = bk + i * 8;
        float4 v = make_float4(0.f, 0.f, 0.f, 0.f);
        if (k < K) v = *reinterpret_cast<const float4*>(Bp + (size_t)k * N + bn0 + bn4);
        *reinterpret_cast<float4*>(&Bs[k * BN + bn4]) = v;
    }
    __syncthreads();

    for (int kt = 0; kt < nk; kt++) {
        float arg[CH];
        float4 brg[2];
        const bool has = (kt + 1 < nk);
        if (has) {
            int kb = (kt + 1) * BK;
#pragma unroll
            for (int j = 0; j < CH; j++) {
                int gk = kb + ak0 + j;
                arg[j] = (gm < C_out && gk < K) ? Ap[(size_t)gm * ldA + gk] : 0.f;
            }
#pragma unroll
            for (int i = 0; i < 2; i++) {
                int gk = kb + bk + i * 8;
                brg[i] = (gk < K)
                             ? *reinterpret_cast<const float4*>(Bp + (size_t)gk * N + bn0 + bn4)
                             : make_float4(0.f, 0.f, 0.f, 0.f);
            }
        }
        // compute current tile
#pragma unroll
        for (int k = 0; k < BK; k++) {
            float a[TM];
            if constexpr (TM == 8) {
                float4 x0 = *reinterpret_cast<const float4*>(&As[k * ASR + tm0]);
                float4 x1 = *reinterpret_cast<const float4*>(&As[k * ASR + tm0 + 4]);
                a[0] = x0.x; a[1] = x0.y; a[2] = x0.z; a[3] = x0.w;
                a[4] = x1.x; a[5] = x1.y; a[6] = x1.z; a[7] = x1.w;
            } else if constexpr (TM == 4) {
                float4 x0 = *reinterpret_cast<const float4*>(&As[k * ASR + tm0]);
                a[0] = x0.x; a[1] = x0.y; a[2] = x0.z; a[3] = x0.w;
            } else {
                float2 x0 = *reinterpret_cast<const float2*>(&As[k * ASR + tm0]);
                a[0] = x0.x; a[1] = x0.y;
            }
            ulonglong2 bv0 = *reinterpret_cast<const ulonglong2*>(&Bs[k * BN + tn0]);
            ulonglong2 bv1 = *reinterpret_cast<const ulonglong2*>(&Bs[k * BN + tn0 + 4]);
            unsigned long long bb[4] = {bv0.x, bv0.y, bv1.x, bv1.y};
#pragma unroll
            for (int i = 0; i < TM; i++) {
                unsigned long long ap = pack2(a[i], a[i]);
#pragma unroll
                for (int j = 0; j < 4; j++) fma2(acc[i][j], ap, bb[j]);
            }
        }
        __syncthreads();
        if (has) {
#pragma unroll
            for (int j = 0; j < CH; j++) As[(ak0 + j) * ASR + am] = arg[j];
#pragma unroll
            for (int i = 0; i < 2; i++)
                *reinterpret_cast<float4*>(&Bs[(bk + i * 8) * BN + bn4]) = brg[i];
            __syncthreads();
        }
    }

    const bool accf = (flags & 1);
    const bool fin = (flags & 2);
    if (!fin) {
        float* Cb = Cout + (size_t)ho * C_out * N;
#pragma unroll
        for (int i = 0; i < TM; i++) {
            int m = bm0 + tm0 + i;
            if (m >= C_out) break;
            float bs = bias[m];
            float* cp = Cb + (size_t)m * N + bn0 + tn0;
            float2 p0 = unpack2(acc[i][0]), p1 = unpack2(acc[i][1]);
            float2 p2 = unpack2(acc[i][2]), p3 = unpack2(acc[i][3]);
            float4 v0 = make_float4(p0.x + bs, p0.y + bs, p1.x + bs, p1.y + bs);
            float4 v1 = make_float4(p2.x + bs, p2.y + bs, p3.x + bs, p3.y + bs);
            if (accf) {
                float4 q0 = *reinterpret_cast<const float4*>(cp);
                float4 q1 = *reinterpret_cast<const float4*>(cp + 4);
                v0.x += q0.x; v0.y += q0.y; v0.z += q0.z; v0.w += q0.w;
                v1.x += q1.x; v1.y += q1.y; v1.z += q1.z; v1.w += q1.w;
            }
            *reinterpret_cast<float4*>(cp) = v0;
            *reinterpret_cast<float4*>(cp + 4) = v1;
        }
    } else {
        // final output: out[b][m][ho][l] = d_out[b*27648 + m*54 + ho*18 + l], n=b*18+l
#pragma unroll
        for (int i = 0; i < TM; i++) {
            int m = bm0 + tm0 + i;
            if (m >= C_out) break;
            float bs = bias[m];
            float2 pr[4] = {unpack2(acc[i][0]), unpack2(acc[i][1]),
                            unpack2(acc[i][2]), unpack2(acc[i][3])};
            float vals[8] = {pr[0].x, pr[0].y, pr[1].x, pr[1].y,
                             pr[2].x, pr[2].y, pr[3].x, pr[3].y};
#pragma unroll
            for (int e = 0; e < 8; e++) {
                int n = bn0 + tn0 + e;
                int b = n / 18;
                int l = n - b * 18;
                size_t adr = (size_t)b * 27648 + (size_t)m * 54 + ho * 18 + l;
                float v = vals[e] + bs;
                if (accf) v += Cout[adr];
                Cout[adr] = v;
            }
        }
    }
}

// ---------------- host launcher ----------------
extern "C" void kernel_launch(void* const* d_in, const int* in_sizes, int n_in,
                              void* d_out, int out_size) {
    const float* x   = (const float*)d_in[0];
    const float* W0a = (const float*)d_in[1];
    const float* b0a = (const float*)d_in[2];
    const float* Wl0 = (const float*)d_in[3];
    const float* bl0 = (const float*)d_in[4];
    const float* W0b = (const float*)d_in[5];
    const float* b0b = (const float*)d_in[6];
    const float* Wr0 = (const float*)d_in[7];
    const float* br0 = (const float*)d_in[8];
    const float* W0c = (const float*)d_in[9];
    const float* b0c = (const float*)d_in[10];
    const float* W1  = (const float*)d_in[11];
    const float* b1  = (const float*)d_in[12];
    const float* Wl1 = (const float*)d_in[13];
    const float* bl1 = (const float*)d_in[14];
    const float* W2  = (const float*)d_in[15];
    const float* b2  = (const float*)d_in[16];
    const float* Wra = (const float*)d_in[17];
    const float* bra = (const float*)d_in[18];
    const float* Wa  = (const float*)d_in[19];
    const float* ba  = (const float*)d_in[20];
    const float* W3  = (const float*)d_in[21];
    const float* b3  = (const float*)d_in[22];
    const float* Wl2 = (const float*)d_in[23];
    const float* bl2 = (const float*)d_in[24];
    const float* W4  = (const float*)d_in[25];
    const float* b4  = (const float*)d_in[26];
    const float* Wrb = (const float*)d_in[27];
    const float* brb = (const float*)d_in[28];
    const float* Wb  = (const float*)d_in[29];
    const float* bb  = (const float*)d_in[30];

    const int B = in_sizes[0] / (5 * 127);
    const int N81 = B * 81, N41 = B * 41, N18 = B * 18;

    float *t0, *t1, *t2, *t3, *t5, *t6, *t7, *t8, *t9, *t10, *t12;
    float *wp0b, *wp1, *wp2, *wp3, *wp4, *wpb;
    cudaGetSymbolAddress((void**)&t0, g_t0);
    cudaGetSymbolAddress((void**)&t1, g_t1);
    cudaGetSymbolAddress((void**)&t2, g_t2);
    cudaGetSymbolAddress((void**)&t3, g_t3);
    cudaGetSymbolAddress((void**)&t5, g_t5);
    cudaGetSymbolAddress((void**)&t6, g_t6);
    cudaGetSymbolAddress((void**)&t7, g_t7);
    cudaGetSymbolAddress((void**)&t8, g_t8);
    cudaGetSymbolAddress((void**)&t9, g_t9);
    cudaGetSymbolAddress((void**)&t10, g_t10);
    cudaGetSymbolAddress((void**)&t12, g_t12);
    cudaGetSymbolAddress((void**)&wp0b, g_wp0b);
    cudaGetSymbolAddress((void**)&wp1, g_wp1);
    cudaGetSymbolAddress((void**)&wp2, g_wp2);
    cudaGetSymbolAddress((void**)&wp3, g_wp3);
    cudaGetSymbolAddress((void**)&wp4, g_wp4);
    cudaGetSymbolAddress((void**)&wpb, g_wpb);

    // fold conv weights [O,I,KH,1] -> [O, KH*I]
    auto perm = [](const float* w, float* wp, int O, int C, int KH) {
        int tot = O * C * KH;
        permute_w_kernel<<<(tot + 255) / 256, 256>>>(w, wp, O, C, KH);
    };
    perm(W0b, wp0b, 25, 5, 3);
    perm(W1, wp1, 75, 25, 3);
    perm(W2, wp2, 150, 75, 3);
    perm(W3, wp3, 300, 150, 2);
    perm(W4, wp4, 512, 300, 2);
    perm(Wb, wpb, 512, 150, 3);

    // ---- block 0 ----
    conv0a_kernel<<<(B * 127 + 255) / 256, 256>>>(x, W0a, b0a, t0, B);
    lin_kernel<<<(25 * B + 7) / 8, 256>>>(t0, Wl0, bl0, t1, 25 * B, 127, 81, 132, 8, 1, 0, B);
    conv_gemm_kernel<32, 2><<<dim3(N81 / 128, 1, 5), 256>>>(wp0b, b0b, t1, t2, 5, 25, 3, 1, 5, N81, 0);
    lin_kernel<<<(5 * B + 7) / 8, 256>>>(x, Wr0, br0, t3, 5 * B, 127, 81, 132, 8, 0, 5, B);
    conv_gemm_kernel<32, 2><<<dim3(N81 / 128, 1, 5), 256>>>(W0c, b0c, t3, t2, 1, 25, 1, 0, 5, N81, 1);
    // t2 = x1

    // ---- block 1 ----
    conv_gemm_kernel<32, 2><<<dim3(N81 / 128, 3, 5), 256>>>(wp1, b1, t2, t5, 25, 75, 3, 1, 5, N81, 0);
    lin_kernel<<<(375 * B + 63) / 64, 256>>>(t5, Wl1, bl1, t6, 375 * B, 81, 41, 84, 64, 1, 0, B);
    conv_gemm_kernel<64, 4><<<dim3(N41 / 128, 3, 5), 256>>>(wp2, b2, t6, t7, 75, 150, 3, 1, 5, N41, 0);
    lin_kernel<<<(125 * B + 63) / 64, 256>>>(t2, Wra, bra, t8, 125 * B, 81, 41, 84, 64, 0, 0, B);
    conv_gemm_kernel<64, 4><<<dim3(N41 / 128, 3, 5), 256>>>(Wa, ba, t8, t7, 25, 150, 1, 0, 5, N41, 1);
    // t7 = x2

    // ---- block 2 ----
    conv_gemm_kernel<128, 8><<<dim3(N41 / 128, 3, 4), 256>>>(wp3, b3, t7, t9, 150, 300, 2, 0, 5, N41, 0);
    lin_kernel<<<(1200 * B + 63) / 64, 256>>>(t9, Wl2, bl2, t10, 1200 * B, 41, 18, 44, 64, 1, 0, B);
    conv_gemm_kernel<128, 8><<<dim3(N18 / 128, 4, 3), 256>>>(wp4, b4, t10, (float*)d_out, 300, 512, 2, 0, 4, N18, 2);
    lin_kernel<<<(750 * B + 63) / 64, 256>>>(t7, Wrb, brb, t12, 750 * B, 41, 18, 44, 64, 0, 0, B);
    conv_gemm_kernel<128, 8><<<dim3(N18 / 128, 4, 3), 256>>>(wpb, bb, t12, (float*)d_out, 150, 512, 3, 0, 5, N18, 3);
}

// round 4
// speedup vs baseline: 1.4246x; 1.4246x over previous
#include <cuda_runtime.h>

// ----------------------------------------------------------------------------
// complex_feature_renet — GB300 sm_103a, round 3
// Layout [H][C][L][B] (B fastest). Convs: per-h GEMM (M=C_out, K=khv*C_in,
// N=L*B). Linears: grouped GEMM (M=O, K, N=B per group). Unified FFMA2
// (fma.rn.f32x2) register-tiled mainloop, TM=8 x TN=8, BN=128, BK=16.
// ----------------------------------------------------------------------------

#define BFIX 1024

// activations, [H][C][L][B]
__device__ float g_xT [5 * 127 * BFIX];            // x transposed [h][l][b]
__device__ float g_t0 [5 * 5   * 127 * BFIX];      // conv0a out
__device__ float g_t1 [5 * 5   * 81  * BFIX];      // lin0 out
__device__ float g_t2 [5 * 25  * 81  * BFIX];      // x1
__device__ float g_t3 [5 * 1   * 81  * BFIX];      // lin r0 out
__device__ float g_t5 [5 * 75  * 81  * BFIX];      // conv1 out
__device__ float g_t6 [5 * 75  * 41  * BFIX];      // lin1 out
__device__ float g_t7 [5 * 150 * 41  * BFIX];      // x2
__device__ float g_t8 [5 * 25  * 41  * BFIX];      // lin ra out
__device__ float g_t9 [4 * 300 * 41  * BFIX];      // conv3 out
__device__ float g_t10[4 * 300 * 18  * BFIX];      // lin2 out
__device__ float g_t12[5 * 150 * 18  * BFIX];      // lin rb out
__device__ float g_t13[3 * 512 * 18  * BFIX];      // final pre-transpose

// folded conv weights wp[o][dh][i]
__device__ float g_wp0b[25  * 15 ];
__device__ float g_wp1 [75  * 75 ];
__device__ float g_wp2 [150 * 225];
__device__ float g_wp3 [300 * 300];
__device__ float g_wp4 [512 * 600];
__device__ float g_wpb [512 * 450];

// ---------------- f32x2 helpers ----------------
__device__ __forceinline__ unsigned long long pack2(float x, float y) {
    unsigned long long r;
    asm("mov.b64 %0, {%1, %2};" : "=l"(r) : "f"(x), "f"(y));
    return r;
}
__device__ __forceinline__ void fma2(unsigned long long& c, unsigned long long a,
                                     unsigned long long b) {
    asm("fma.rn.f32x2 %0, %1, %2, %0;" : "+l"(c) : "l"(a), "l"(b));
}
__device__ __forceinline__ float2 unpack2(unsigned long long v) {
    float2 r;
    asm("mov.b64 {%0, %1}, %2;" : "=f"(r.x), "=f"(r.y) : "l"(v));
    return r;
}

// ---------------- fused weight fold (all 6 convs, 1 launch) ----------------
struct P6 {
    const float *s0, *s1, *s2, *s3, *s4, *s5;
    float *d0, *d1, *d2, *d3, *d4, *d5;
};
__global__ void permute_all_kernel(P6 p) {
    int idx = blockIdx.x * blockDim.x + threadIdx.x;
    const float* s; float* d; int O, C, KH, base;
    if (idx < 375)        { s = p.s0; d = p.d0; O = 25;  C = 5;   KH = 3; base = 0; }
    else if (idx < 6000)  { s = p.s1; d = p.d1; O = 75;  C = 25;  KH = 3; base = 375; }
    else if (idx < 39750) { s = p.s2; d = p.d2; O = 150; C = 75;  KH = 3; base = 6000; }
    else if (idx < 129750){ s = p.s3; d = p.d3; O = 300; C = 150; KH = 2; base = 39750; }
    else if (idx < 436950){ s = p.s4; d = p.d4; O = 512; C = 300; KH = 2; base = 129750; }
    else if (idx < 667350){ s = p.s5; d = p.d5; O = 512; C = 150; KH = 3; base = 436950; }
    else return;
    int local = idx - base;
    int o = local / (KH * C);
    int rem = local - o * (KH * C);
    int dh = rem / C;
    int i = rem - dh * C;
    d[local] = s[(o * C + i) * KH + dh];
}

// ---------------- x transpose: x[b][5][127] -> xT[h][l][b] ----------------
__global__ void xpose_kernel(const float* __restrict__ x, float* __restrict__ xT,
                             int B) {
    __shared__ float sm[32][33];
    int h = blockIdx.z;
    int l0 = blockIdx.x * 32, b0 = blockIdx.y * 32;
    int tx = threadIdx.x, ty = threadIdx.y;  // 32 x 8
#pragma unroll
    for (int j = 0; j < 4; j++) {
        int b = b0 + ty + j * 8, l = l0 + tx;
        if (l < 127) sm[ty + j * 8][tx] = x[((size_t)b * 5 + h) * 127 + l];
    }
    __syncthreads();
#pragma unroll
    for (int j = 0; j < 4; j++) {
        int l = l0 + ty + j * 8, b = b0 + tx;
        if (l < 127) xT[((size_t)h * 127 + l) * B + b] = sm[tx][ty + j * 8];
    }
}

// ---------------- conv0a: xT[h][l][b] -> t0[ho][c][l][b] ----------------
__global__ void conv0a_kernel(const float* __restrict__ xT, const float* __restrict__ w,
                              const float* __restrict__ bias, float* __restrict__ out,
                              int B) {
    int n = blockIdx.x * blockDim.x + threadIdx.x;  // over l*B
    int N = 127 * B;
    if (n >= N) return;
    float xv[5];
#pragma unroll
    for (int h = 0; h < 5; h++) xv[h] = xT[(size_t)h * N + n];
    float wv[5][3];
#pragma unroll
    for (int c = 0; c < 5; c++)
#pragma unroll
        for (int dh = 0; dh < 3; dh++) wv[c][dh] = w[c * 3 + dh];
#pragma unroll
    for (int ho = 0; ho < 5; ho++) {
#pragma unroll
        for (int c = 0; c < 5; c++) {
            float acc = bias[c];
#pragma unroll
            for (int dh = 0; dh < 3; dh++) {
                int hi = ho + dh - 1;
                if (hi >= 0 && hi < 5) acc = fmaf(wv[c][dh], xv[hi], acc);
            }
            out[(size_t)(ho * 5 + c) * N + n] = acc;
        }
    }
}

// ---------------- unified GEMM (conv + grouped linear) ----------------
// CONV:  B-matrix rows [h][C_in][N], Wp[C_out][KH*C_in]; grid (N/128, my, H_out)
// LIN :  per-group GEMM, A=W[O][K]; grid (groups * (B/128), my, 1)
// flags: bit0 = accumulate into C, bit1 = relu
template <int BM, bool LINM>
__global__ __launch_bounds__(BM * 2, (BM == 128 ? 2 : BM == 64 ? 4 : BM == 48 ? 4 : 6))
void gemm_kernel(const float* __restrict__ A, int lda,
                 const float* __restrict__ bias,
                 const float* __restrict__ Bb, float* __restrict__ Cb,
                 int C_in, int C_out, int KH, int pad, int H_in,
                 int ldB, int flags) {
    constexpr int NT = BM * 2, BN = 128, BK = 16, ASR = BM + 4;
    constexpr int F4 = (512 + NT - 1) / NT;  // float4 loads per thread for B tile
    __shared__ __align__(16) float As[BK * ASR];
    __shared__ __align__(16) float Bs[BK * BN];

    const int t = threadIdx.x;
    const int bm0 = blockIdx.y * BM;

    int K;
    const float* Ap;
    const float* Bp;
    float* Cp;
    if (LINM) {
        K = C_in;
        int nb = ldB >> 7;
        int g = blockIdx.x / nb;
        int nbi = blockIdx.x - g * nb;
        Ap = A;
        Bp = Bb + (size_t)g * K * ldB + nbi * BN;
        Cp = Cb + (size_t)g * C_out * ldB + nbi * BN;
    } else {
        int ho = blockIdx.z;
        int hs = ho - pad;
        int h0 = hs > 0 ? hs : 0;
        int he = hs + KH; if (he > H_in) he = H_in;
        K = (he - h0) * C_in;
        Ap = A + (h0 - hs) * C_in;
        Bp = Bb + (size_t)h0 * C_in * ldB + (size_t)blockIdx.x * BN;
        Cp = Cb + (size_t)ho * C_out * ldB + (size_t)blockIdx.x * BN;
    }

    const int am = t >> 1;
    const int ak0 = (t & 1) * 8;
    const int gm = bm0 + am;
    const int tidm = t / 16, tidn = t % 16;
    const int tm0 = tidm * 8, tn0 = tidn * 8;

    unsigned long long acc[8][4];
#pragma unroll
    for (int i = 0; i < 8; i++)
#pragma unroll
        for (int j = 0; j < 4; j++) acc[i][j] = 0ull;

    const int nk = (K + BK - 1) / BK;

    // tile 0 -> smem
#pragma unroll
    for (int j = 0; j < 8; j++) {
        int gk = ak0 + j;
        float v = (gm < C_out && gk < K) ? Ap[(size_t)gm * lda + gk] : 0.f;
        As[gk * ASR + am] = v;
    }
#pragma unroll
    for (int i = 0; i < F4; i++) {
        int e = t + i * NT;
        if (e < 512) {
            int k = e >> 5, c4 = (e & 31) * 4;
            float4 v = make_float4(0.f, 0.f, 0.f, 0.f);
            if (k < K) v = *reinterpret_cast<const float4*>(Bp + (size_t)k * ldB + c4);
            *reinterpret_cast<float4*>(&Bs[k * BN + c4]) = v;
        }
    }
    __syncthreads();

    for (int kt = 0; kt < nk; kt++) {
        float arg[8];
        float4 brg[F4];
        const bool has = (kt + 1 < nk);
        if (has) {
            int kb = (kt + 1) * BK;
#pragma unroll
            for (int j = 0; j < 8; j++) {
                int gk = kb + ak0 + j;
                arg[j] = (gm < C_out && gk < K) ? Ap[(size_t)gm * lda + gk] : 0.f;
            }
#pragma unroll
            for (int i = 0; i < F4; i++) {
                int e = t + i * NT;
                if (e < 512) {
                    int k = kb + (e >> 5), c4 = (e & 31) * 4;
                    brg[i] = (k < K)
                                 ? *reinterpret_cast<const float4*>(Bp + (size_t)k * ldB + c4)
                                 : make_float4(0.f, 0.f, 0.f, 0.f);
                }
            }
        }
#pragma unroll
        for (int k = 0; k < BK; k++) {
            float4 x0 = *reinterpret_cast<const float4*>(&As[k * ASR + tm0]);
            float4 x1 = *reinterpret_cast<const float4*>(&As[k * ASR + tm0 + 4]);
            float a[8] = {x0.x, x0.y, x0.z, x0.w, x1.x, x1.y, x1.z, x1.w};
            ulonglong2 bv0 = *reinterpret_cast<const ulonglong2*>(&Bs[k * BN + tn0]);
            ulonglong2 bv1 = *reinterpret_cast<const ulonglong2*>(&Bs[k * BN + tn0 + 4]);
            unsigned long long bb[4] = {bv0.x, bv0.y, bv1.x, bv1.y};
#pragma unroll
            for (int i = 0; i < 8; i++) {
                unsigned long long ap = pack2(a[i], a[i]);
#pragma unroll
                for (int j = 0; j < 4; j++) fma2(acc[i][j], ap, bb[j]);
            }
        }
        __syncthreads();
        if (has) {
#pragma unroll
            for (int j = 0; j < 8; j++) As[(ak0 + j) * ASR + am] = arg[j];
#pragma unroll
            for (int i = 0; i < F4; i++) {
                int e = t + i * NT;
                if (e < 512) {
                    int k = e >> 5, c4 = (e & 31) * 4;
                    *reinterpret_cast<float4*>(&Bs[k * BN + c4]) = brg[i];
                }
            }
            __syncthreads();
        }
    }

    const bool accf = (flags & 1);
    const bool relu = (flags & 2);
#pragma unroll
    for (int i = 0; i < 8; i++) {
        int m = bm0 + tm0 + i;
        if (m >= C_out) break;
        float bs = bias[m];
        float* cp = Cp + (size_t)m * ldB + tn0;
        float2 p0 = unpack2(acc[i][0]), p1 = unpack2(acc[i][1]);
        float2 p2 = unpack2(acc[i][2]), p3 = unpack2(acc[i][3]);
        float4 v0 = make_float4(p0.x + bs, p0.y + bs, p1.x + bs, p1.y + bs);
        float4 v1 = make_float4(p2.x + bs, p2.y + bs, p3.x + bs, p3.y + bs);
        if (accf) {
            float4 q0 = *reinterpret_cast<const float4*>(cp);
            float4 q1 = *reinterpret_cast<const float4*>(cp + 4);
            v0.x += q0.x; v0.y += q0.y; v0.z += q0.z; v0.w += q0.w;
            v1.x += q1.x; v1.y += q1.y; v1.z += q1.z; v1.w += q1.w;
        }
        if (relu) {
            v0.x = fmaxf(v0.x, 0.f); v0.y = fmaxf(v0.y, 0.f);
            v0.z = fmaxf(v0.z, 0.f); v0.w = fmaxf(v0.w, 0.f);
            v1.x = fmaxf(v1.x, 0.f); v1.y = fmaxf(v1.y, 0.f);
            v1.z = fmaxf(v1.z, 0.f); v1.w = fmaxf(v1.w, 0.f);
        }
        *reinterpret_cast<float4*>(cp) = v0;
        *reinterpret_cast<float4*>(cp + 4) = v1;
    }
}

// ---------------- final transpose t13[ho][m][l][b] -> out[b][m][ho][l] -----
__global__ __launch_bounds__(256) void ftrans_kernel(const float* __restrict__ t13,
                                                     float* __restrict__ out, int B) {
    __shared__ float sm[128 * 19];
    int b0 = blockIdx.x * 128;
    int m = blockIdx.y, ho = blockIdx.z;
    int t = threadIdx.x;
    for (int idx = t; idx < 18 * 128; idx += 256) {
        int l = idx >> 7, b = idx & 127;
        sm[b * 19 + l] = t13[((size_t)(ho * 512 + m) * 18 + l) * B + b0 + b];
    }
    __syncthreads();
    for (int idx = t; idx < 128 * 18; idx += 256) {
        int b = idx / 18, l = idx - 18 * b;
        out[((size_t)(b0 + b) * 512 + m) * 54 + ho * 18 + l] = sm[b * 19 + l];
    }
}

// ---------------- host launcher ----------------
extern "C" void kernel_launch(void* const* d_in, const int* in_sizes, int n_in,
                              void* d_out, int out_size) {
    const float* x   = (const float*)d_in[0];
    const float* W0a = (const float*)d_in[1];
    const float* b0a = (const float*)d_in[2];
    const float* Wl0 = (const float*)d_in[3];
    const float* bl0 = (const float*)d_in[4];
    const float* W0b = (const float*)d_in[5];
    const float* b0b = (const float*)d_in[6];
    const float* Wr0 = (const float*)d_in[7];
    const float* br0 = (const float*)d_in[8];
    const float* W0c = (const float*)d_in[9];
    const float* b0c = (const float*)d_in[10];
    const float* W1  = (const float*)d_in[11];
    const float* b1  = (const float*)d_in[12];
    const float* Wl1 = (const float*)d_in[13];
    const float* bl1 = (const float*)d_in[14];
    const float* W2  = (const float*)d_in[15];
    const float* b2  = (const float*)d_in[16];
    const float* Wra = (const float*)d_in[17];
    const float* bra = (const float*)d_in[18];
    const float* Wa  = (const float*)d_in[19];
    const float* ba  = (const float*)d_in[20];
    const float* W3  = (const float*)d_in[21];
    const float* b3  = (const float*)d_in[22];
    const float* Wl2 = (const float*)d_in[23];
    const float* bl2 = (const float*)d_in[24];
    const float* W4  = (const float*)d_in[25];
    const float* b4  = (const float*)d_in[26];
    const float* Wrb = (const float*)d_in[27];
    const float* brb = (const float*)d_in[28];
    const float* Wb  = (const float*)d_in[29];
    const float* bb  = (const float*)d_in[30];

    const int B = in_sizes[0] / (5 * 127);
    const int nb = B / 128;
    const int N81 = 81 * B, N41 = 41 * B, N18 = 18 * B;

    float *xT, *t0, *t1, *t2, *t3, *t5, *t6, *t7, *t8, *t9, *t10, *t12, *t13;
    float *wp0b, *wp1, *wp2, *wp3, *wp4, *wpb;
    cudaGetSymbolAddress((void**)&xT, g_xT);
    cudaGetSymbolAddress((void**)&t0, g_t0);
    cudaGetSymbolAddress((void**)&t1, g_t1);
    cudaGetSymbolAddress((void**)&t2, g_t2);
    cudaGetSymbolAddress((void**)&t3, g_t3);
    cudaGetSymbolAddress((void**)&t5, g_t5);
    cudaGetSymbolAddress((void**)&t6, g_t6);
    cudaGetSymbolAddress((void**)&t7, g_t7);
    cudaGetSymbolAddress((void**)&t8, g_t8);
    cudaGetSymbolAddress((void**)&t9, g_t9);
    cudaGetSymbolAddress((void**)&t10, g_t10);
    cudaGetSymbolAddress((void**)&t12, g_t12);
    cudaGetSymbolAddress((void**)&t13, g_t13);
    cudaGetSymbolAddress((void**)&wp0b, g_wp0b);
    cudaGetSymbolAddress((void**)&wp1, g_wp1);
    cudaGetSymbolAddress((void**)&wp2, g_wp2);
    cudaGetSymbolAddress((void**)&wp3, g_wp3);
    cudaGetSymbolAddress((void**)&wp4, g_wp4);
    cudaGetSymbolAddress((void**)&wpb, g_wpb);

    // weight fold (1 launch)
    P6 p; p.s0 = W0b; p.s1 = W1; p.s2 = W2; p.s3 = W3; p.s4 = W4; p.s5 = Wb;
    p.d0 = wp0b; p.d1 = wp1; p.d2 = wp2; p.d3 = wp3; p.d4 = wp4; p.d5 = wpb;
    permute_all_kernel<<<(667350 + 255) / 256, 256>>>(p);

    // x -> xT
    xpose_kernel<<<dim3(4, B / 32, 5), dim3(32, 8)>>>(x, xT, B);

    // ---- block 0 ----
    conv0a_kernel<<<(127 * B + 255) / 256, 256>>>(xT, W0a, b0a, t0, B);
    gemm_kernel<48, true><<<dim3(25 * nb, 2, 1), 96>>>(Wl0, 127, bl0, t0, t1,
                                                       127, 81, 0, 0, 0, B, 2);
    gemm_kernel<32, false><<<dim3(N81 / 128, 1, 5), 64>>>(wp0b, 15, b0b, t1, t2,
                                                          5, 25, 3, 1, 5, N81, 0);
    gemm_kernel<48, true><<<dim3(5 * nb, 2, 1), 96>>>(Wr0, 127, br0, xT, t3,
                                                      127, 81, 0, 0, 0, B, 0);
    gemm_kernel<32, false><<<dim3(N81 / 128, 1, 5), 64>>>(W0c, 1, b0c, t3, t2,
                                                          1, 25, 1, 0, 5, N81, 1);
    // t2 = x1

    // ---- block 1 ----
    gemm_kernel<48, false><<<dim3(N81 / 128, 2, 5), 96>>>(wp1, 75, b1, t2, t5,
                                                          25, 75, 3, 1, 5, N81, 0);
    gemm_kernel<48, true><<<dim3(375 * nb, 1, 1), 96>>>(Wl1, 81, bl1, t5, t6,
                                                        81, 41, 0, 0, 0, B, 2);
    gemm_kernel<32, false><<<dim3(N41 / 128, 5, 5), 64>>>(wp2, 225, b2, t6, t7,
                                                          75, 150, 3, 1, 5, N41, 0);
    gemm_kernel<48, true><<<dim3(125 * nb, 1, 1), 96>>>(Wra, 81, bra, t2, t8,
                                                        81, 41, 0, 0, 0, B, 0);
    gemm_kernel<32, false><<<dim3(N41 / 128, 5, 5), 64>>>(Wa, 25, ba, t8, t7,
                                                          25, 150, 1, 0, 5, N41, 1);
    // t7 = x2

    // ---- block 2 ----
    gemm_kernel<64, false><<<dim3(N41 / 128, 5, 4), 128>>>(wp3, 300, b3, t7, t9,
                                                           150, 300, 2, 0, 5, N41, 0);
    gemm_kernel<32, true><<<dim3(1200 * nb, 1, 1), 64>>>(Wl2, 41, bl2, t9, t10,
                                                         41, 18, 0, 0, 0, B, 2);
    gemm_kernel<128, false><<<dim3(N18 / 128, 4, 3), 256>>>(wp4, 600, b4, t10, t13,
                                                            300, 512, 2, 0, 4, N18, 0);
    gemm_kernel<32, true><<<dim3(750 * nb, 1, 1), 64>>>(Wrb, 41, brb, t7, t12,
                                                        41, 18, 0, 0, 0, B, 0);
    gemm_kernel<128, false><<<dim3(N18 / 128, 4, 3), 256>>>(wpb, 450, bb, t12, t13,
                                                            150, 512, 3, 0, 5, N18, 1);
    // t13 -> d_out
    ftrans_kernel<<<dim3(B / 128, 512, 3), 256>>>(t13, (float*)d_out, B);
}